// round 1
// baseline (speedup 1.0000x reference)
#include <cuda_runtime.h>
#include <cuda_bf16.h>

// Dead-code-eliminated forward: the cross-attention has exactly ONE kv token,
// so softmax == 1.0 and o == v, making pred/act independent of x_batch and the
// entire 4-layer transformer stack. Live chain per batch element:
//   ctx  = context_batch[b] @ ctx_w + ctx_b
//   v    = ctx  @ ca_wv + ca_bv
//   last = v    @ ca_wo + ca_bo
//   pred = last @ pred_w[sid] + pred_b[sid]
//   act  = last @ act_w [sid] + act_b [sid]
//
// Input indices (metadata order):
//  0 x_batch(i32) 1 context_batch(f32,16x2) 2 specialist_ids(i32,16)
//  3 emb 4 wqkv 5 bqkv 6 wo 7 bo 8 ln1_g 9 ln1_b 10 w1 11 b1 12 w2 13 b2
// 14 ln2_g 15 ln2_b 16 ctx_w(2x512) 17 ctx_b(512)
// 18 ca_wq 19 ca_bq 20 ca_wk 21 ca_bk 22 ca_wv(512x512) 23 ca_bv(512)
// 24 ca_wo(512x512) 25 ca_bo(512)
// 26 pred_w(4x512x64) 27 pred_b(4x64) 28 act_w(4x512x64) 29 act_b(4x64)
// Output: [pred(16x64), act(16x64)] f32, 2048 elements.

#define D_MODEL 512
#define NB 16
#define NOUT 64

__global__ __launch_bounds__(256, 2)
void hivemind_tail_kernel(
    const float* __restrict__ cb,      // (16,2)
    const int*   __restrict__ sid,     // (16,)
    const float* __restrict__ ctx_w,   // (2,512)
    const float* __restrict__ ctx_b,   // (512,)
    const float* __restrict__ ca_wv,   // (512,512)
    const float* __restrict__ ca_bv,   // (512,)
    const float* __restrict__ ca_wo,   // (512,512)
    const float* __restrict__ ca_bo,   // (512,)
    const float* __restrict__ pred_w,  // (4,512,64)
    const float* __restrict__ pred_b,  // (4,64)
    const float* __restrict__ act_w,   // (4,512,64)
    const float* __restrict__ act_b,   // (4,64)
    float* __restrict__ out)           // 2048
{
    __shared__ float s_ctx[D_MODEL];
    __shared__ float s_v[D_MODEL];
    __shared__ float s_last[D_MODEL];

    const int b = blockIdx.x;
    const int t = threadIdx.x;      // 256 threads

    // 1. ctx = context_batch[b] @ ctx_w + ctx_b   (2 -> 512)
    const float c0 = cb[b * 2 + 0];
    const float c1 = cb[b * 2 + 1];
    #pragma unroll
    for (int d = t; d < D_MODEL; d += 256)
        s_ctx[d] = fmaf(c0, ctx_w[d], fmaf(c1, ctx_w[D_MODEL + d], ctx_b[d]));
    __syncthreads();

    // 2. v = ctx @ ca_wv + ca_bv  (512x512 matvec, coalesced over d)
    #pragma unroll
    for (int d = t; d < D_MODEL; d += 256) {
        float acc = ca_bv[d];
        #pragma unroll 8
        for (int k = 0; k < D_MODEL; ++k)
            acc = fmaf(s_ctx[k], ca_wv[k * D_MODEL + d], acc);
        s_v[d] = acc;
    }
    __syncthreads();

    // 3. last = v @ ca_wo + ca_bo
    #pragma unroll
    for (int d = t; d < D_MODEL; d += 256) {
        float acc = ca_bo[d];
        #pragma unroll 8
        for (int k = 0; k < D_MODEL; ++k)
            acc = fmaf(s_v[k], ca_wo[k * D_MODEL + d], acc);
        s_last[d] = acc;
    }
    __syncthreads();

    // 4. pred / act heads: 128 outputs total (64 pred + 64 act), threads 0..127
    const int s = sid[b];
    if (t < 2 * NOUT) {
        const int  o     = t & (NOUT - 1);
        const bool isAct = (t >= NOUT);
        const float* w    = (isAct ? act_w : pred_w) + (size_t)s * D_MODEL * NOUT;
        const float* bias = (isAct ? act_b : pred_b) + s * NOUT;
        float acc = bias[o];
        #pragma unroll 8
        for (int k = 0; k < D_MODEL; ++k)
            acc = fmaf(s_last[k], w[k * NOUT + o], acc);
        out[(isAct ? NB * NOUT : 0) + b * NOUT + o] = acc;
    }
}

extern "C" void kernel_launch(void* const* d_in, const int* in_sizes, int n_in,
                              void* d_out, int out_size) {
    const float* cb     = (const float*)d_in[1];
    const int*   sid    = (const int*)  d_in[2];
    const float* ctx_w  = (const float*)d_in[16];
    const float* ctx_b  = (const float*)d_in[17];
    const float* ca_wv  = (const float*)d_in[22];
    const float* ca_bv  = (const float*)d_in[23];
    const float* ca_wo  = (const float*)d_in[24];
    const float* ca_bo  = (const float*)d_in[25];
    const float* pred_w = (const float*)d_in[26];
    const float* pred_b = (const float*)d_in[27];
    const float* act_w  = (const float*)d_in[28];
    const float* act_b  = (const float*)d_in[29];
    float* out = (float*)d_out;

    hivemind_tail_kernel<<<NB, 256>>>(cb, sid, ctx_w, ctx_b,
                                      ca_wv, ca_bv, ca_wo, ca_bo,
                                      pred_w, pred_b, act_w, act_b, out);
}

// round 2
// speedup vs baseline: 3.1618x; 3.1618x over previous
#include <cuda_runtime.h>
#include <cuda_bf16.h>

// Dead-code-eliminated forward (see R1): single-kv-token cross-attention makes
// softmax==1 and o==v, so outputs depend only on:
//   ctx  = context_batch[b] @ ctx_w + ctx_b        (2   -> 512)
//   v    = ctx  @ ca_wv + ca_bv                    (512 -> 512)
//   last = v    @ ca_wo + ca_bo                    (512 -> 512)
//   pred = last @ pred_w[sid] + pred_b[sid]        (512 -> 64)
//   act  = last @ act_w [sid] + act_b [sid]        (512 -> 64)
//
// R2: split K across warps + batches across blocks for latency hiding.
// 3 kernels chained through __device__ scratch (no allocation).

#define D_MODEL 512
#define NB 16
#define NOUT 64

__device__ float g_v[NB * D_MODEL];
__device__ float g_last[NB * D_MODEL];

// ---------------------------------------------------------------------------
// K1: v[b][d] = ca_bv[d] + sum_k ctx[b][k] * Wv[k][d]
// grid = 64: blockIdx = bg*16 + dt  (bg: batch group of 4, dt: 32-wide d tile)
// 256 threads = 32 d-lanes x 8 k-splits (64 k each)
// ---------------------------------------------------------------------------
__global__ __launch_bounds__(256)
void k_matvec_v(const float* __restrict__ cb,
                const float* __restrict__ ctx_w,
                const float* __restrict__ ctx_b,
                const float* __restrict__ Wv,
                const float* __restrict__ bv)
{
    __shared__ float s_in[4][D_MODEL];
    __shared__ float s_red[8][4][32];

    const int bg = blockIdx.x >> 4;    // 0..3
    const int dt = blockIdx.x & 15;    // 0..15
    const int t  = threadIdx.x;

    // build ctx rows for this block's 4 batches
    for (int idx = t; idx < 4 * D_MODEL; idx += 256) {
        const int b = idx >> 9;
        const int k = idx & (D_MODEL - 1);
        const float c0 = cb[(bg * 4 + b) * 2 + 0];
        const float c1 = cb[(bg * 4 + b) * 2 + 1];
        s_in[b][k] = fmaf(c0, ctx_w[k], fmaf(c1, ctx_w[D_MODEL + k], ctx_b[k]));
    }
    __syncthreads();

    const int dl = t & 31;
    const int ks = t >> 5;
    const int d  = dt * 32 + dl;
    const int kb = ks * 64;

    float a0 = 0.f, a1 = 0.f, a2 = 0.f, a3 = 0.f;
    #pragma unroll 8
    for (int i = 0; i < 64; ++i) {
        const int k = kb + i;
        const float w = Wv[k * D_MODEL + d];
        a0 = fmaf(s_in[0][k], w, a0);
        a1 = fmaf(s_in[1][k], w, a1);
        a2 = fmaf(s_in[2][k], w, a2);
        a3 = fmaf(s_in[3][k], w, a3);
    }
    s_red[ks][0][dl] = a0;
    s_red[ks][1][dl] = a1;
    s_red[ks][2][dl] = a2;
    s_red[ks][3][dl] = a3;
    __syncthreads();

    if (t < 128) {
        const int b   = t >> 5;
        const int dl2 = t & 31;
        float s = 0.f;
        #pragma unroll
        for (int j = 0; j < 8; ++j) s += s_red[j][b][dl2];
        g_v[(bg * 4 + b) * D_MODEL + dt * 32 + dl2] = s + bv[dt * 32 + dl2];
    }
}

// ---------------------------------------------------------------------------
// K2: last[b][d] = ca_bo[d] + sum_k v[b][k] * Wo[k][d]   (same structure)
// ---------------------------------------------------------------------------
__global__ __launch_bounds__(256)
void k_matvec_last(const float* __restrict__ Wo,
                   const float* __restrict__ bo)
{
    __shared__ float s_in[4][D_MODEL];
    __shared__ float s_red[8][4][32];

    const int bg = blockIdx.x >> 4;
    const int dt = blockIdx.x & 15;
    const int t  = threadIdx.x;

    for (int idx = t; idx < 4 * D_MODEL; idx += 256) {
        const int b = idx >> 9;
        const int k = idx & (D_MODEL - 1);
        s_in[b][k] = g_v[(bg * 4 + b) * D_MODEL + k];
    }
    __syncthreads();

    const int dl = t & 31;
    const int ks = t >> 5;
    const int d  = dt * 32 + dl;
    const int kb = ks * 64;

    float a0 = 0.f, a1 = 0.f, a2 = 0.f, a3 = 0.f;
    #pragma unroll 8
    for (int i = 0; i < 64; ++i) {
        const int k = kb + i;
        const float w = Wo[k * D_MODEL + d];
        a0 = fmaf(s_in[0][k], w, a0);
        a1 = fmaf(s_in[1][k], w, a1);
        a2 = fmaf(s_in[2][k], w, a2);
        a3 = fmaf(s_in[3][k], w, a3);
    }
    s_red[ks][0][dl] = a0;
    s_red[ks][1][dl] = a1;
    s_red[ks][2][dl] = a2;
    s_red[ks][3][dl] = a3;
    __syncthreads();

    if (t < 128) {
        const int b   = t >> 5;
        const int dl2 = t & 31;
        float s = 0.f;
        #pragma unroll
        for (int j = 0; j < 8; ++j) s += s_red[j][b][dl2];
        g_last[(bg * 4 + b) * D_MODEL + dt * 32 + dl2] = s + bo[dt * 32 + dl2];
    }
}

// ---------------------------------------------------------------------------
// K3: heads. grid = 32: blockIdx = b*2 + head (0=pred, 1=act)
// 256 threads = 64 outputs x 4 k-splits (128 k each)
// out layout: [pred(16x64), act(16x64)]
// ---------------------------------------------------------------------------
__global__ __launch_bounds__(256)
void k_heads(const int*   __restrict__ sid,
             const float* __restrict__ pred_w,
             const float* __restrict__ pred_b,
             const float* __restrict__ act_w,
             const float* __restrict__ act_b,
             float* __restrict__ out)
{
    __shared__ float s_last[D_MODEL];
    __shared__ float s_part[4][NOUT];

    const int b    = blockIdx.x >> 1;
    const int head = blockIdx.x & 1;
    const int t    = threadIdx.x;

    for (int k = t; k < D_MODEL; k += 256)
        s_last[k] = g_last[b * D_MODEL + k];
    __syncthreads();

    const int s = sid[b];
    const float* w    = (head ? act_w : pred_w) + (size_t)s * D_MODEL * NOUT;
    const float* bias = (head ? act_b : pred_b) + s * NOUT;

    const int o  = t & (NOUT - 1);
    const int kh = t >> 6;           // 0..3
    const int kb = kh * 128;

    float acc = 0.f;
    #pragma unroll 8
    for (int i = 0; i < 128; ++i) {
        const int k = kb + i;
        acc = fmaf(s_last[k], w[k * NOUT + o], acc);
    }
    s_part[kh][o] = acc;
    __syncthreads();

    if (t < NOUT) {
        float r = s_part[0][t] + s_part[1][t] + s_part[2][t] + s_part[3][t] + bias[t];
        out[head * NB * NOUT + b * NOUT + t] = r;
    }
}

// ---------------------------------------------------------------------------
extern "C" void kernel_launch(void* const* d_in, const int* in_sizes, int n_in,
                              void* d_out, int out_size) {
    const float* cb     = (const float*)d_in[1];
    const int*   sid    = (const int*)  d_in[2];
    const float* ctx_w  = (const float*)d_in[16];
    const float* ctx_b  = (const float*)d_in[17];
    const float* ca_wv  = (const float*)d_in[22];
    const float* ca_bv  = (const float*)d_in[23];
    const float* ca_wo  = (const float*)d_in[24];
    const float* ca_bo  = (const float*)d_in[25];
    const float* pred_w = (const float*)d_in[26];
    const float* pred_b = (const float*)d_in[27];
    const float* act_w  = (const float*)d_in[28];
    const float* act_b  = (const float*)d_in[29];
    float* out = (float*)d_out;

    k_matvec_v<<<64, 256>>>(cb, ctx_w, ctx_b, ca_wv, ca_bv);
    k_matvec_last<<<64, 256>>>(ca_wo, ca_bo);
    k_heads<<<32, 256>>>(sid, pred_w, pred_b, act_w, act_b, out);
}

// round 3
// speedup vs baseline: 3.9298x; 1.2429x over previous
#include <cuda_runtime.h>
#include <cuda_bf16.h>

// Fully-collapsed forward. The live chain (see R1/R2 analysis) is linear in
// context_batch, so the batch dimension reduces to 2 scalars (c0, c1):
//   u_i = r_i @ Wv            (r0,r1 = rows of ctx_w, r2 = ctx_b; u2 += bv)
//   w_i = u_i @ Wo            (w2 += bo)
//   P_i[s,h] = w_i @ Whead[s,h]   (P2 += bias)
//   out[h,b,:] = c0[b]*P0[sid[b],h] + c1[b]*P1[sid[b],h] + P2[sid[b],h]
// One kernel, 16 co-resident blocks, 2 grid barriers (monotonic counters —
// graph-replay safe, never reset).

#define D_MODEL 512
#define NB 16
#define NOUT 64
#define NBLK 16

__device__ float g_u[3 * D_MODEL];
__device__ float g_w[3 * D_MODEL];
__device__ unsigned g_bar[2];   // zero-initialized, monotonically increasing

__device__ __forceinline__ void grid_barrier(int i) {
    __syncthreads();
    if (threadIdx.x == 0) {
        __threadfence();                           // release my block's writes
        unsigned t = atomicAdd(&g_bar[i], 1u);
        unsigned R = (t / NBLK + 1u) * NBLK;       // release epoch boundary
        while (*((volatile unsigned*)&g_bar[i]) < R) { }
    }
    __syncthreads();
    __threadfence();                               // acquire
}

__global__ __launch_bounds__(256, 1)
void hivemind_fused(
    const float* __restrict__ cb,      // (16,2)
    const int*   __restrict__ sid,     // (16,)
    const float* __restrict__ ctx_w,   // (2,512)
    const float* __restrict__ ctx_b,   // (512,)
    const float* __restrict__ Wv,      // (512,512)
    const float* __restrict__ bv,      // (512,)
    const float* __restrict__ Wo,      // (512,512)
    const float* __restrict__ bo,      // (512,)
    const float* __restrict__ pred_w,  // (4,512,64)
    const float* __restrict__ pred_b,  // (4,64)
    const float* __restrict__ act_w,   // (4,512,64)
    const float* __restrict__ act_b,   // (4,64)
    float* __restrict__ out)           // [pred(16x64), act(16x64)]
{
    __shared__ float s_vec[3][D_MODEL];        // input vectors per stage
    __shared__ float s_red[8][3][32];          // stage A/B reduction
    __shared__ float s_red2[4][3][NOUT];       // stage C reduction
    __shared__ float s_P[3][NOUT];
    __shared__ float s_cb[NB * 2];
    __shared__ int   s_sid[NB];

    const int t   = threadIdx.x;
    const int blk = blockIdx.x;

    // ---------------- Stage A: u_i = r_i @ Wv  (blocks 0..15 = d-tiles) ----
    for (int k = t; k < D_MODEL; k += 256) {
        s_vec[0][k] = ctx_w[k];
        s_vec[1][k] = ctx_w[D_MODEL + k];
        s_vec[2][k] = ctx_b[k];
    }
    __syncthreads();
    {
        const int dl = t & 31, ks = t >> 5;
        const int d  = blk * 32 + dl;
        float a0 = 0.f, a1 = 0.f, a2 = 0.f;
        #pragma unroll 8
        for (int i = 0; i < 64; ++i) {
            const int k = ks * 64 + i;
            const float w = Wv[k * D_MODEL + d];
            a0 = fmaf(s_vec[0][k], w, a0);
            a1 = fmaf(s_vec[1][k], w, a1);
            a2 = fmaf(s_vec[2][k], w, a2);
        }
        s_red[ks][0][dl] = a0;
        s_red[ks][1][dl] = a1;
        s_red[ks][2][dl] = a2;
    }
    __syncthreads();
    if (t < 96) {
        const int i = t >> 5, dl = t & 31, d = blk * 32 + dl;
        float s = 0.f;
        #pragma unroll
        for (int j = 0; j < 8; ++j) s += s_red[j][i][dl];
        if (i == 2) s += bv[d];
        g_u[i * D_MODEL + d] = s;
    }
    grid_barrier(0);

    // ---------------- Stage B: w_i = u_i @ Wo ------------------------------
    for (int k = t; k < D_MODEL; k += 256) {
        s_vec[0][k] = g_u[k];
        s_vec[1][k] = g_u[D_MODEL + k];
        s_vec[2][k] = g_u[2 * D_MODEL + k];
    }
    __syncthreads();
    {
        const int dl = t & 31, ks = t >> 5;
        const int d  = blk * 32 + dl;
        float a0 = 0.f, a1 = 0.f, a2 = 0.f;
        #pragma unroll 8
        for (int i = 0; i < 64; ++i) {
            const int k = ks * 64 + i;
            const float w = Wo[k * D_MODEL + d];
            a0 = fmaf(s_vec[0][k], w, a0);
            a1 = fmaf(s_vec[1][k], w, a1);
            a2 = fmaf(s_vec[2][k], w, a2);
        }
        s_red[ks][0][dl] = a0;
        s_red[ks][1][dl] = a1;
        s_red[ks][2][dl] = a2;
    }
    __syncthreads();
    if (t < 96) {
        const int i = t >> 5, dl = t & 31, d = blk * 32 + dl;
        float s = 0.f;
        #pragma unroll
        for (int j = 0; j < 8; ++j) s += s_red[j][i][dl];
        if (i == 2) s += bo[d];
        g_w[i * D_MODEL + d] = s;
    }
    grid_barrier(1);

    // ---------------- Stage C+D: heads + batch combine ---------------------
    if (blk >= 8) return;
    const int s = blk >> 1;            // specialist
    const int h = blk & 1;             // 0=pred, 1=act
    const float* Wh = (h ? act_w : pred_w) + (size_t)s * D_MODEL * NOUT;
    const float* bh = (h ? act_b : pred_b) + s * NOUT;

    for (int k = t; k < D_MODEL; k += 256) {
        s_vec[0][k] = g_w[k];
        s_vec[1][k] = g_w[D_MODEL + k];
        s_vec[2][k] = g_w[2 * D_MODEL + k];
    }
    if (t < NB * 2) s_cb[t] = cb[t];
    if (t < NB)     s_sid[t] = sid[t];
    __syncthreads();
    {
        const int o = t & 63, ks = t >> 6;     // 4 k-splits of 128
        float a0 = 0.f, a1 = 0.f, a2 = 0.f;
        #pragma unroll 8
        for (int i = 0; i < 128; ++i) {
            const int k = ks * 128 + i;
            const float w = Wh[k * NOUT + o];
            a0 = fmaf(s_vec[0][k], w, a0);
            a1 = fmaf(s_vec[1][k], w, a1);
            a2 = fmaf(s_vec[2][k], w, a2);
        }
        s_red2[ks][0][o] = a0;
        s_red2[ks][1][o] = a1;
        s_red2[ks][2][o] = a2;
    }
    __syncthreads();
    if (t < 192) {
        const int i = t >> 6, o = t & 63;
        float p = s_red2[0][i][o] + s_red2[1][i][o] + s_red2[2][i][o] + s_red2[3][i][o];
        if (i == 2) p += bh[o];
        s_P[i][o] = p;
    }
    __syncthreads();
    if (t < NOUT) {
        const float p0 = s_P[0][t], p1 = s_P[1][t], p2 = s_P[2][t];
        #pragma unroll
        for (int b = 0; b < NB; ++b) {
            if (s_sid[b] == s)
                out[h * NB * NOUT + b * NOUT + t] =
                    fmaf(s_cb[b * 2], p0, fmaf(s_cb[b * 2 + 1], p1, p2));
        }
    }
}

extern "C" void kernel_launch(void* const* d_in, const int* in_sizes, int n_in,
                              void* d_out, int out_size) {
    const float* cb     = (const float*)d_in[1];
    const int*   sid    = (const int*)  d_in[2];
    const float* ctx_w  = (const float*)d_in[16];
    const float* ctx_b  = (const float*)d_in[17];
    const float* ca_wv  = (const float*)d_in[22];
    const float* ca_bv  = (const float*)d_in[23];
    const float* ca_wo  = (const float*)d_in[24];
    const float* ca_bo  = (const float*)d_in[25];
    const float* pred_w = (const float*)d_in[26];
    const float* pred_b = (const float*)d_in[27];
    const float* act_w  = (const float*)d_in[28];
    const float* act_b  = (const float*)d_in[29];
    float* out = (float*)d_out;

    hivemind_fused<<<NBLK, 256>>>(cb, sid, ctx_w, ctx_b,
                                  ca_wv, ca_bv, ca_wo, ca_bo,
                                  pred_w, pred_b, act_w, act_b, out);
}

// round 6
// speedup vs baseline: 5.0885x; 1.2948x over previous
#include <cuda_runtime.h>
#include <cuda_bf16.h>

// Collapsed forward (linear in context_batch -> batch dim reduces to 2 scalars):
//   u_i = r_i @ Wv   (r0,r1 = rows of ctx_w, r2 = ctx_b; u2 += bv)
//   w_i = u_i @ Wo   (w2 += bo)
//   P_i[s,h] = w_i @ Whead[s,h]  (+bias into P2)
//   out[h,b,:] = c0[b]*P0 + c1[b]*P1 + P2   (selected by sid[b])
// One kernel, 128 co-resident blocks (1/SM), 3 monotonic grid barriers.
// Work split so every thread's load chain is only 8-16 deep (latency hiding).

#define D_MODEL 512
#define NB 16
#define NOUT 64
#define NBLK 128

__device__ float g_u[3 * D_MODEL];
__device__ float g_w[3 * D_MODEL];
__device__ float g_ph[64 * 3 * NOUT];      // [sh*8+kq][i][o] head partials
__device__ unsigned g_bar[3];              // monotonic, graph-replay safe

__device__ __forceinline__ void grid_barrier(int i) {
    __syncthreads();
    if (threadIdx.x == 0) {
        __threadfence();
        unsigned t = atomicAdd(&g_bar[i], 1u);
        unsigned R = (t / NBLK + 1u) * NBLK;
        while (*((volatile unsigned*)&g_bar[i]) < R) { }
    }
    __syncthreads();
    __threadfence();
}

__device__ __forceinline__ float shfl_red8(float v) {
    // reduce over lane bits 2..4 (8 k-splits inside a warp)
    v += __shfl_xor_sync(0xffffffffu, v, 4);
    v += __shfl_xor_sync(0xffffffffu, v, 8);
    v += __shfl_xor_sync(0xffffffffu, v, 16);
    return v;
}

__global__ __launch_bounds__(256, 1)
void hivemind_fused(
    const float* __restrict__ cb,      // (16,2)
    const int*   __restrict__ sid,     // (16,)
    const float* __restrict__ ctx_w,   // (2,512)
    const float* __restrict__ ctx_b,   // (512,)
    const float* __restrict__ Wv,      // (512,512)
    const float* __restrict__ bv,      // (512,)
    const float* __restrict__ Wo,      // (512,512)
    const float* __restrict__ bo,      // (512,)
    const float* __restrict__ pred_w,  // (4,512,64)
    const float* __restrict__ pred_b,  // (4,64)
    const float* __restrict__ act_w,   // (4,512,64)
    const float* __restrict__ act_b,   // (4,64)
    float* __restrict__ out)           // [pred(16x64), act(16x64)]
{
    __shared__ float s_vec[3][D_MODEL];
    __shared__ float s_part[8][3][4];
    __shared__ float s_w[3][64];
    __shared__ float s_red2[4][3][NOUT];
    __shared__ float s_P[3][NOUT];
    __shared__ float s_cb[NB * 2];
    __shared__ int   s_sid[NB];

    const int t   = threadIdx.x;
    const int blk = blockIdx.x;
    const int dl  = t & 3;          // d-lane within block (4 columns)
    const int ks  = t >> 2;         // k-split 0..63 (8 k each)
    const int wid = t >> 5;

    // ================= Stage A: u_i = r_i @ Wv ==========================
    for (int k = t; k < D_MODEL; k += 256) {
        s_vec[0][k] = ctx_w[k];
        s_vec[1][k] = ctx_w[D_MODEL + k];
        s_vec[2][k] = ctx_b[k];
    }
    __syncthreads();
    {
        const int d  = blk * 4 + dl;
        const int k0 = ks * 8;
        float a0 = 0.f, a1 = 0.f, a2 = 0.f;
        #pragma unroll
        for (int i = 0; i < 8; ++i) {
            const int k = k0 + i;
            const float w = Wv[k * D_MODEL + d];
            a0 = fmaf(s_vec[0][k], w, a0);
            a1 = fmaf(s_vec[1][k], w, a1);
            a2 = fmaf(s_vec[2][k], w, a2);
        }
        a0 = shfl_red8(a0); a1 = shfl_red8(a1); a2 = shfl_red8(a2);
        if ((t & 31) < 4) {
            s_part[wid][0][dl] = a0;
            s_part[wid][1][dl] = a1;
            s_part[wid][2][dl] = a2;
        }
    }
    __syncthreads();
    if (t < 12) {
        const int i = t >> 2, d2 = t & 3, d = blk * 4 + d2;
        float s = 0.f;
        #pragma unroll
        for (int j = 0; j < 8; ++j) s += s_part[j][i][d2];
        if (i == 2) s += bv[d];
        g_u[i * D_MODEL + d] = s;
    }
    grid_barrier(0);

    // ================= Stage B: w_i = u_i @ Wo ==========================
    for (int k = t; k < D_MODEL; k += 256) {
        s_vec[0][k] = g_u[k];
        s_vec[1][k] = g_u[D_MODEL + k];
        s_vec[2][k] = g_u[2 * D_MODEL + k];
    }
    __syncthreads();
    {
        const int d  = blk * 4 + dl;
        const int k0 = ks * 8;
        float a0 = 0.f, a1 = 0.f, a2 = 0.f;
        #pragma unroll
        for (int i = 0; i < 8; ++i) {
            const int k = k0 + i;
            const float w = Wo[k * D_MODEL + d];
            a0 = fmaf(s_vec[0][k], w, a0);
            a1 = fmaf(s_vec[1][k], w, a1);
            a2 = fmaf(s_vec[2][k], w, a2);
        }
        a0 = shfl_red8(a0); a1 = shfl_red8(a1); a2 = shfl_red8(a2);
        if ((t & 31) < 4) {
            s_part[wid][0][dl] = a0;
            s_part[wid][1][dl] = a1;
            s_part[wid][2][dl] = a2;
        }
    }
    __syncthreads();
    if (t < 12) {
        const int i = t >> 2, d2 = t & 3, d = blk * 4 + d2;
        float s = 0.f;
        #pragma unroll
        for (int j = 0; j < 8; ++j) s += s_part[j][i][d2];
        if (i == 2) s += bo[d];
        g_w[i * D_MODEL + d] = s;
    }
    grid_barrier(1);

    // ================= Stage C: head partials ===========================
    // blocks 0..63: sh = blk>>3 (specialist*2+head), kq = blk&7 (64-k chunk)
    if (blk < 64) {
        const int sh = blk >> 3, kq = blk & 7;
        const int s  = sh >> 1, h = sh & 1;
        const float* Wh = (h ? act_w : pred_w) + (size_t)s * D_MODEL * NOUT;

        if (t < 192) {
            const int i = t >> 6, j = t & 63;
            s_w[i][j] = g_w[i * D_MODEL + kq * 64 + j];
        }
        __syncthreads();
        {
            const int o = t & 63, ksub = t >> 6;   // 4 sub-splits x 16 k
            float a0 = 0.f, a1 = 0.f, a2 = 0.f;
            #pragma unroll
            for (int i = 0; i < 16; ++i) {
                const int kl = ksub * 16 + i;
                const float w = Wh[(kq * 64 + kl) * NOUT + o];
                a0 = fmaf(s_w[0][kl], w, a0);
                a1 = fmaf(s_w[1][kl], w, a1);
                a2 = fmaf(s_w[2][kl], w, a2);
            }
            s_red2[ksub][0][o] = a0;
            s_red2[ksub][1][o] = a1;
            s_red2[ksub][2][o] = a2;
        }
        __syncthreads();
        if (t < 192) {
            const int i = t >> 6, o = t & 63;
            float p = s_red2[0][i][o] + s_red2[1][i][o]
                    + s_red2[2][i][o] + s_red2[3][i][o];
            g_ph[(sh * 8 + kq) * 192 + i * 64 + o] = p;
        }
    }
    grid_barrier(2);

    // ================= Stage D: combine + output ========================
    if (blk >= 8) return;
    const int sh = blk, s = sh >> 1, h = sh & 1;
    const float* bh = (h ? act_b : pred_b) + s * NOUT;

    if (t < 192) {
        const int i = t >> 6, o = t & 63;
        float p = 0.f;
        #pragma unroll
        for (int kq = 0; kq < 8; ++kq)
            p += g_ph[(sh * 8 + kq) * 192 + i * 64 + o];
        if (i == 2) p += bh[o];
        s_P[i][o] = p;
    }
    if (t >= 192 && t < 192 + NB * 2) s_cb[t - 192] = cb[t - 192];
    if (t >= 224 && t < 224 + NB)     s_sid[t - 224] = sid[t - 224];
    __syncthreads();

    if (t < NOUT) {
        const float p0 = s_P[0][t], p1 = s_P[1][t], p2 = s_P[2][t];
        #pragma unroll
        for (int b = 0; b < NB; ++b) {
            if (s_sid[b] == s)
                out[h * NB * NOUT + b * NOUT + t] =
                    fmaf(s_cb[b * 2], p0, fmaf(s_cb[b * 2 + 1], p1, p2));
        }
    }
}

extern "C" void kernel_launch(void* const* d_in, const int* in_sizes, int n_in,
                              void* d_out, int out_size) {
    const float* cb     = (const float*)d_in[1];
    const int*   sid    = (const int*)  d_in[2];
    const float* ctx_w  = (const float*)d_in[16];
    const float* ctx_b  = (const float*)d_in[17];
    const float* ca_wv  = (const float*)d_in[22];
    const float* ca_bv  = (const float*)d_in[23];
    const float* ca_wo  = (const float*)d_in[24];
    const float* ca_bo  = (const float*)d_in[25];
    const float* pred_w = (const float*)d_in[26];
    const float* pred_b = (const float*)d_in[27];
    const float* act_w  = (const float*)d_in[28];
    const float* act_b  = (const float*)d_in[29];
    float* out = (float*)d_out;

    hivemind_fused<<<NBLK, 256>>>(cb, sid, ctx_w, ctx_b,
                                  ca_wv, ca_bv, ca_wo, ca_bo,
                                  pred_w, pred_b, act_w, act_b, out);
}